// round 6
// baseline (speedup 1.0000x reference)
#include <cuda_runtime.h>
#include <math.h>
#include <stdint.h>

#define N_NODES 100000
#define D_FEAT  128
#define E_EDGES 600000
#define C_OUT   256
#define K_TOT   256

// ---------------- scratch (no allocs allowed; __device__ globals) -------------
__device__ __align__(16) float g_sums[(size_t)N_NODES * D_FEAT];   // 51.2 MB
__device__ float g_cnt[N_NODES];
__device__ int   g_idx64;                            // 1 if edge_index is int64

// ---------------- packed f32x2 helpers (Blackwell FFMA2 via PTX) --------------
__device__ __forceinline__ void ffma2(unsigned long long& d, unsigned long long a, unsigned long long b) {
    asm("fma.rn.f32x2 %0, %1, %2, %0;" : "+l"(d) : "l"(a), "l"(b));
}
__device__ __forceinline__ unsigned long long pack2(float lo, float hi) {
    unsigned long long r;
    asm("mov.b64 %0, {%1, %2};" : "=l"(r) : "f"(lo), "f"(hi));
    return r;
}
__device__ __forceinline__ void unpack2(float& lo, float& hi, unsigned long long v) {
    asm("mov.b64 {%0, %1}, %2;" : "=f"(lo), "=f"(hi) : "l"(v));
}

// ---------------- index-width detection --------------------------------------
// If the buffer is really int32, an int64 read combines two random ints in
// [0,1e5): v = lo + hi*2^32 >= 2^32 unless hi==0 (p ~ 1e-5 per element).
__global__ void detect_kernel(const long long* __restrict__ ei) {
    int ok = 1;
#pragma unroll
    for (int i = 0; i < 8; i++) {
        long long v = ei[i];
        if (v < 0 || v >= (long long)N_NODES) ok = 0;
    }
    g_idx64 = ok;
}

// ---------------- zero scratch ------------------------------------------------
__global__ void zero_kernel() {
    int i = blockIdx.x * blockDim.x + threadIdx.x;
    const int TOT4 = N_NODES * D_FEAT / 4;   // 3.2M float4
    if (i < TOT4) reinterpret_cast<float4*>(g_sums)[i] = make_float4(0.f, 0.f, 0.f, 0.f);
    if (i < N_NODES) g_cnt[i] = 0.f;
}

// ---------------- vector reduction helper ------------------------------------
__device__ __forceinline__ void red_add_v4(float* p, float4 v) {
    asm volatile("red.global.add.v4.f32 [%0], {%1, %2, %3, %4};"
                 :: "l"(p), "f"(v.x), "f"(v.y), "f"(v.z), "f"(v.w)
                 : "memory");
}

// ---------------- edge scatter: one warp per edge, one RED.128 per lane ------
__global__ void scatter_kernel(const float* __restrict__ x,
                               const long long* __restrict__ ei) {
    int gid  = blockIdx.x * blockDim.x + threadIdx.x;
    int e    = gid >> 5;
    int lane = gid & 31;
    if (e >= E_EDGES) return;

    int r, c;
    if (g_idx64) {
        r = (int)ei[e];
        c = (int)ei[E_EDGES + e];
    } else {
        const int* e32 = (const int*)ei;
        r = e32[e];
        c = e32[E_EDGES + e];
    }
    if (r == c) return;   // self-loop removal

    const float4 v = *reinterpret_cast<const float4*>(x + (size_t)c * D_FEAT + lane * 4);
    red_add_v4(g_sums + (size_t)r * D_FEAT + lane * 4, v);
    if (lane == 0) atomicAdd(&g_cnt[r], 1.0f);
}

// ---------------- fused (mean || x) @ W + bias + row-L2-normalize ------------
// Block tile: BM=64 nodes x BN=256 (full output row), BK=16, 256 threads.
// Thread tile 8x8 via FFMA2 (packed f32x2): 32 FFMA2 per kk per thread.
// ty = tid>>5 (8 row-groups), tx = tid&31 (32 col-groups). Threads sharing ty
// form one warp -> warp-shfl row L2 norm in the epilogue.
#define BM 64
#define BK 16
#define APAD 4            // row stride 68 floats = 272B: 16B-aligned
#define NT (K_TOT / BK)   // 16 k-tiles

__global__ __launch_bounds__(256, 2) void gemm_kernel(const float* __restrict__ x,
                                                      const float* __restrict__ W,
                                                      const float* __restrict__ bias,
                                                      float* __restrict__ out) {
    __shared__ __align__(16) float As[2][BK][BM + APAD];   // [buf][k][m]
    __shared__ __align__(16) float Bs[2][BK][C_OUT];       // [buf][k][n]

    const int tid = threadIdx.x;
    const int tx  = tid & 31;             // col group: cols tx*8 .. tx*8+7
    const int ty  = tid >> 5;             // row group: rows ty*8 .. ty*8+7 (== warp id)
    const int node0 = blockIdx.x * BM;

    // A-load role: thread handles row am, k-quad akq (4 consecutive k)
    const int am  = tid >> 2;             // 0..63
    const int akq = (tid & 3) * 4;        // 0,4,8,12
    const int amg = node0 + am;
    const bool a_ok = (amg < N_NODES);
    float inv_cnt = 1.0f;
    if (a_ok) inv_cnt = 1.0f / fmaxf(g_cnt[amg], 1.0f);

    // acc2[i][j]: packed pair = cols (2j, 2j+1) of row i of the 8x8 tile
    unsigned long long acc2[8][4];
    const unsigned long long zz = pack2(0.f, 0.f);
#pragma unroll
    for (int i = 0; i < 8; i++)
#pragma unroll
        for (int j = 0; j < 4; j++) acc2[i][j] = zz;

    // ---- tile fetch helpers (to registers) ----
    float4 aReg;            // A: 1 float4 per thread
    float4 bReg[4];         // B: 4 float4 per thread

    auto fetch = [&](int t) {
        int k = t * BK + akq;
        if (a_ok) {
            if (k < D_FEAT) {
                aReg = *reinterpret_cast<const float4*>(g_sums + (size_t)amg * D_FEAT + k);
                aReg.x *= inv_cnt; aReg.y *= inv_cnt; aReg.z *= inv_cnt; aReg.w *= inv_cnt;
            } else {
                aReg = *reinterpret_cast<const float4*>(x + (size_t)amg * D_FEAT + (k - D_FEAT));
            }
        } else {
            aReg = make_float4(0.f, 0.f, 0.f, 0.f);
        }
#pragma unroll
        for (int j = 0; j < 4; j++) {
            int f  = j * 256 + tid;       // float4 index in 16x256 tile (coalesced)
            int kk = f >> 6;
            int n4 = f & 63;
            bReg[j] = *reinterpret_cast<const float4*>(W + (size_t)(t * BK + kk) * C_OUT + n4 * 4);
        }
    };
    auto stage = [&](int b) {
        As[b][akq + 0][am] = aReg.x;
        As[b][akq + 1][am] = aReg.y;
        As[b][akq + 2][am] = aReg.z;
        As[b][akq + 3][am] = aReg.w;
#pragma unroll
        for (int j = 0; j < 4; j++) {
            int f  = j * 256 + tid;
            int kk = f >> 6;
            int n4 = f & 63;
            *reinterpret_cast<float4*>(&Bs[b][kk][n4 * 4]) = bReg[j];
        }
    };

    // ---- pipeline: prologue ----
    fetch(0);
    stage(0);
    __syncthreads();

    int buf = 0;
#pragma unroll 1
    for (int t = 0; t < NT; t++) {
        if (t + 1 < NT) fetch(t + 1);

        // compute on buf: 8x8 outer product per kk via FFMA2
#pragma unroll
        for (int kk = 0; kk < BK; kk++) {
            float4 a0 = *reinterpret_cast<float4*>(&As[buf][kk][ty * 8]);
            float4 a1 = *reinterpret_cast<float4*>(&As[buf][kk][ty * 8 + 4]);
            ulonglong2 bp0 = *reinterpret_cast<ulonglong2*>(&Bs[buf][kk][tx * 8]);
            ulonglong2 bp1 = *reinterpret_cast<ulonglong2*>(&Bs[buf][kk][tx * 8 + 4]);
            unsigned long long bp[4] = {bp0.x, bp0.y, bp1.x, bp1.y};
            float av[8] = {a0.x, a0.y, a0.z, a0.w, a1.x, a1.y, a1.z, a1.w};
#pragma unroll
            for (int i = 0; i < 8; i++) {
                unsigned long long ap = pack2(av[i], av[i]);
#pragma unroll
                for (int j = 0; j < 4; j++)
                    ffma2(acc2[i][j], ap, bp[j]);
            }
        }

        if (t + 1 < NT) {
            stage(buf ^ 1);
            __syncthreads();
            buf ^= 1;
        }
    }

    // ---- epilogue: + bias, row L2 norm (warp owns rows ty*8..+7), store ----
    float4 bv0 = *reinterpret_cast<const float4*>(bias + tx * 8);
    float4 bv1 = *reinterpret_cast<const float4*>(bias + tx * 8 + 4);
    float bb[8] = {bv0.x, bv0.y, bv0.z, bv0.w, bv1.x, bv1.y, bv1.z, bv1.w};

    float acc[8][8];
    float ss[8];
#pragma unroll
    for (int i = 0; i < 8; i++) {
        float s = 0.f;
#pragma unroll
        for (int j = 0; j < 4; j++) {
            float lo, hi;
            unpack2(lo, hi, acc2[i][j]);
            acc[i][2 * j]     = lo + bb[2 * j];
            acc[i][2 * j + 1] = hi + bb[2 * j + 1];
            s += acc[i][2 * j] * acc[i][2 * j] + acc[i][2 * j + 1] * acc[i][2 * j + 1];
        }
        ss[i] = s;
    }
    // warp reduction across the 32 tx-threads (whole 256-col row)
#pragma unroll
    for (int off = 16; off > 0; off >>= 1) {
#pragma unroll
        for (int i = 0; i < 8; i++)
            ss[i] += __shfl_xor_sync(0xFFFFFFFFu, ss[i], off);
    }

#pragma unroll
    for (int i = 0; i < 8; i++) {
        int mg = node0 + ty * 8 + i;
        if (mg < N_NODES) {
            float inv = 1.0f / fmaxf(sqrtf(ss[i]), 1e-12f);
            float4 o0, o1;
            o0.x = acc[i][0] * inv; o0.y = acc[i][1] * inv;
            o0.z = acc[i][2] * inv; o0.w = acc[i][3] * inv;
            o1.x = acc[i][4] * inv; o1.y = acc[i][5] * inv;
            o1.z = acc[i][6] * inv; o1.w = acc[i][7] * inv;
            float* op = out + (size_t)mg * C_OUT + tx * 8;
            *reinterpret_cast<float4*>(op)     = o0;
            *reinterpret_cast<float4*>(op + 4) = o1;
        }
    }
}

// ---------------- launch ------------------------------------------------------
extern "C" void kernel_launch(void* const* d_in, const int* in_sizes, int n_in,
                              void* d_out, int out_size) {
    const float*     x    = (const float*)d_in[0];      // [100000,128]
    const long long* ei   = (const long long*)d_in[1];  // [2,600000]
    const float*     W    = (const float*)d_in[2];      // [256,256]
    const float*     bias = (const float*)d_in[3];      // [1,256]
    float*           out  = (float*)d_out;              // [100000,256]

    detect_kernel<<<1, 1>>>(ei);

    {
        int tot = N_NODES * D_FEAT / 4;                 // 3.2M
        zero_kernel<<<(tot + 255) / 256, 256>>>();
    }

    {
        long long threads = (long long)E_EDGES * 32;
        scatter_kernel<<<(int)((threads + 255) / 256), 256>>>(x, ei);
    }

    {
        dim3 grid((N_NODES + BM - 1) / BM);             // 1563
        gemm_kernel<<<grid, 256>>>(x, W, bias, out);
    }
}

// round 7
// speedup vs baseline: 2.1352x; 2.1352x over previous
#include <cuda_runtime.h>
#include <cuda_bf16.h>
#include <math.h>
#include <stdint.h>

#define N_NODES 100000
#define D_FEAT  128
#define E_EDGES 600000
#define C_OUT   256

// ---------------- scratch (no allocs allowed; __device__ globals) -------------
__device__ __align__(16) float g_sums[(size_t)N_NODES * D_FEAT];   // 51.2 MB
__device__ float g_cnt[N_NODES];
__device__ int   g_idx64;
// W pre-transposed + bf16 hi/lo split: [n][k] rows of 256 bf16 (512B)
__device__ __align__(16) unsigned char g_Bhi_t[256 * 512];
__device__ __align__(16) unsigned char g_Blo_t[256 * 512];

// ---------------- index-width detection --------------------------------------
__global__ void detect_kernel(const long long* __restrict__ ei) {
    int ok = 1;
#pragma unroll
    for (int i = 0; i < 8; i++) {
        long long v = ei[i];
        if (v < 0 || v >= (long long)N_NODES) ok = 0;
    }
    g_idx64 = ok;
}

// ---------------- zero scratch ------------------------------------------------
__global__ void zero_kernel() {
    int i = blockIdx.x * blockDim.x + threadIdx.x;
    const int TOT4 = N_NODES * D_FEAT / 4;
    if (i < TOT4) reinterpret_cast<float4*>(g_sums)[i] = make_float4(0.f, 0.f, 0.f, 0.f);
    if (i < N_NODES) g_cnt[i] = 0.f;
}

// ---------------- W prep: transpose + bf16 hi/lo split ------------------------
__global__ void prep_w_kernel(const float* __restrict__ W) {
    int n = blockIdx.x;        // 0..255
    int k = threadIdx.x;       // 0..255
    float w = W[k * C_OUT + n];
    __nv_bfloat16 hi = __float2bfloat16(w);
    __nv_bfloat16 lo = __float2bfloat16(w - __bfloat162float(hi));
    reinterpret_cast<__nv_bfloat16*>(g_Bhi_t)[n * 256 + k] = hi;
    reinterpret_cast<__nv_bfloat16*>(g_Blo_t)[n * 256 + k] = lo;
}

// ---------------- vector reduction helper ------------------------------------
__device__ __forceinline__ void red_add_v4(float* p, float4 v) {
    asm volatile("red.global.add.v4.f32 [%0], {%1, %2, %3, %4};"
                 :: "l"(p), "f"(v.x), "f"(v.y), "f"(v.z), "f"(v.w) : "memory");
}

// ---------------- edge scatter: one warp per edge ----------------------------
__global__ void scatter_kernel(const float* __restrict__ x,
                               const long long* __restrict__ ei) {
    int gid  = blockIdx.x * blockDim.x + threadIdx.x;
    int e    = gid >> 5;
    int lane = gid & 31;
    if (e >= E_EDGES) return;

    int r, c;
    if (g_idx64) {
        r = (int)ei[e];
        c = (int)ei[E_EDGES + e];
    } else {
        const int* e32 = (const int*)ei;
        r = e32[e];
        c = e32[E_EDGES + e];
    }
    if (r == c) return;

    const float4 v = *reinterpret_cast<const float4*>(x + (size_t)c * D_FEAT + lane * 4);
    red_add_v4(g_sums + (size_t)r * D_FEAT + lane * 4, v);
    if (lane == 0) atomicAdd(&g_cnt[r], 1.0f);
}

// ---------------- HMMA GEMM: (mean||x) @ W + bias + row-L2-normalize ---------
// BM=64, BN=256, 256 threads = 8 warps as 2(M)x4(N); warp tile 32x64.
// mma.sync m16n8k16 bf16->f32, 3-pass hi/lo split. K chunked 128 x 2.
// smem rows padded to 272B (136 bf16): frag LDS bank = (4r+c)%32, conflict-free.
#define ROWB 272
#define ROWH 136
#define SM_BIAS 0
#define SM_RED  1024
#define SM_AHI  2048
#define SM_ALO  (SM_AHI + 64 * ROWB)      // 19456
#define SM_BHI  (SM_ALO + 64 * ROWB)      // 36864
#define SM_BLO  (SM_BHI + 256 * ROWB)     // 106496
#define SM_TOT  (SM_BLO + 256 * ROWB)     // 176128

__device__ __forceinline__ void mma16816(float d[4], const uint32_t a[4], const uint32_t b[2]) {
    asm volatile("mma.sync.aligned.m16n8k16.row.col.f32.bf16.bf16.f32 "
                 "{%0,%1,%2,%3}, {%4,%5,%6,%7}, {%8,%9}, {%0,%1,%2,%3};"
                 : "+f"(d[0]), "+f"(d[1]), "+f"(d[2]), "+f"(d[3])
                 : "r"(a[0]), "r"(a[1]), "r"(a[2]), "r"(a[3]), "r"(b[0]), "r"(b[1]));
}

__global__ void __launch_bounds__(256) gemm_hmma_kernel(const float* __restrict__ x,
                                                        const float* __restrict__ bias,
                                                        float* __restrict__ out) {
    extern __shared__ __align__(16) unsigned char smem[];
    const int tid = threadIdx.x;
    const int wid = tid >> 5;
    const int lid = tid & 31;
    const int wm  = wid >> 2;            // 0..1 : rows wm*32..+31
    const int wn  = wid & 3;             // 0..3 : cols wn*64..+63
    const int r4  = lid >> 2;            // 0..7
    const int c4  = lid & 3;             // 0..3
    const int node0 = blockIdx.x * 64;

    // stage bias
    reinterpret_cast<float*>(smem + SM_BIAS)[tid] = bias[tid];

    // A staging role: row = tid>>2 (0..63), k-base = (tid&3)*32 within 128-chunk
    const int arow = tid >> 2;
    const int akb  = (tid & 3) * 32;
    const int amg  = node0 + arow;
    const bool a_ok = (amg < N_NODES);
    const float inv_cnt = a_ok ? (1.0f / fmaxf(g_cnt[amg], 1.0f)) : 0.f;

    float acc[2][8][4];
#pragma unroll
    for (int mt = 0; mt < 2; mt++)
#pragma unroll
        for (int nt = 0; nt < 8; nt++)
#pragma unroll
            for (int q = 0; q < 4; q++) acc[mt][nt][q] = 0.f;

    const uint4* gbh = reinterpret_cast<const uint4*>(g_Bhi_t);
    const uint4* gbl = reinterpret_cast<const uint4*>(g_Blo_t);

#pragma unroll 1
    for (int c = 0; c < 2; c++) {
        // ---- stage A (hi/lo split) ----
        {
            const float* asrc = (c == 0) ? (g_sums + (size_t)amg * D_FEAT + akb)
                                         : (x      + (size_t)amg * D_FEAT + akb);
            const float scale = (c == 0) ? inv_cnt : 1.0f;
#pragma unroll
            for (int q = 0; q < 8; q++) {
                float4 v = make_float4(0.f, 0.f, 0.f, 0.f);
                if (a_ok) {
                    v = *reinterpret_cast<const float4*>(asrc + q * 4);
                    v.x *= scale; v.y *= scale; v.z *= scale; v.w *= scale;
                }
                __nv_bfloat16 hx = __float2bfloat16(v.x), hy = __float2bfloat16(v.y);
                __nv_bfloat16 hz = __float2bfloat16(v.z), hw = __float2bfloat16(v.w);
                __nv_bfloat16 lx = __float2bfloat16(v.x - __bfloat162float(hx));
                __nv_bfloat16 ly = __float2bfloat16(v.y - __bfloat162float(hy));
                __nv_bfloat16 lz = __float2bfloat16(v.z - __bfloat162float(hz));
                __nv_bfloat16 lw = __float2bfloat16(v.w - __bfloat162float(hw));
                uint32_t hi0 = (uint32_t)__bfloat16_as_ushort(hx) | ((uint32_t)__bfloat16_as_ushort(hy) << 16);
                uint32_t hi1 = (uint32_t)__bfloat16_as_ushort(hz) | ((uint32_t)__bfloat16_as_ushort(hw) << 16);
                uint32_t lo0 = (uint32_t)__bfloat16_as_ushort(lx) | ((uint32_t)__bfloat16_as_ushort(ly) << 16);
                uint32_t lo1 = (uint32_t)__bfloat16_as_ushort(lz) | ((uint32_t)__bfloat16_as_ushort(lw) << 16);
                uint32_t byt = (uint32_t)(arow * ROWH + akb + q * 4) * 2;
                *reinterpret_cast<uint32_t*>(smem + SM_AHI + byt)     = hi0;
                *reinterpret_cast<uint32_t*>(smem + SM_AHI + byt + 4) = hi1;
                *reinterpret_cast<uint32_t*>(smem + SM_ALO + byt)     = lo0;
                *reinterpret_cast<uint32_t*>(smem + SM_ALO + byt + 4) = lo1;
            }
        }
        // ---- stage B (coalesced copy of 128-bf16 slices) ----
#pragma unroll
        for (int i = 0; i < 16; i++) {
            int f = i * 256 + tid;           // 0..4095
            int n = f >> 4;
            int j = f & 15;
            *reinterpret_cast<uint4*>(smem + SM_BHI + n * ROWB + j * 16) = gbh[n * 32 + c * 16 + j];
            *reinterpret_cast<uint4*>(smem + SM_BLO + n * ROWB + j * 16) = gbl[n * 32 + c * 16 + j];
        }
        __syncthreads();

        // ---- compute: 8 k-steps of 16 ----
#pragma unroll
        for (int ks = 0; ks < 8; ks++) {
            const int kb = ks * 16;
            uint32_t ahi[2][4], alo[2][4];
#pragma unroll
            for (int mt = 0; mt < 2; mt++) {
                int row0 = wm * 32 + mt * 16 + r4;
                uint32_t byt = (uint32_t)(row0 * ROWH + kb + 2 * c4) * 2;
                ahi[mt][0] = *reinterpret_cast<uint32_t*>(smem + SM_AHI + byt);
                ahi[mt][1] = *reinterpret_cast<uint32_t*>(smem + SM_AHI + byt + 8 * ROWB);
                ahi[mt][2] = *reinterpret_cast<uint32_t*>(smem + SM_AHI + byt + 16);
                ahi[mt][3] = *reinterpret_cast<uint32_t*>(smem + SM_AHI + byt + 8 * ROWB + 16);
                alo[mt][0] = *reinterpret_cast<uint32_t*>(smem + SM_ALO + byt);
                alo[mt][1] = *reinterpret_cast<uint32_t*>(smem + SM_ALO + byt + 8 * ROWB);
                alo[mt][2] = *reinterpret_cast<uint32_t*>(smem + SM_ALO + byt + 16);
                alo[mt][3] = *reinterpret_cast<uint32_t*>(smem + SM_ALO + byt + 8 * ROWB + 16);
            }
            uint32_t bhi[8][2], blo[8][2];
#pragma unroll
            for (int nt = 0; nt < 8; nt++) {
                int n = wn * 64 + nt * 8 + r4;
                uint32_t byt = (uint32_t)(n * ROWH + kb + 2 * c4) * 2;
                bhi[nt][0] = *reinterpret_cast<uint32_t*>(smem + SM_BHI + byt);
                bhi[nt][1] = *reinterpret_cast<uint32_t*>(smem + SM_BHI + byt + 16);
                blo[nt][0] = *reinterpret_cast<uint32_t*>(smem + SM_BLO + byt);
                blo[nt][1] = *reinterpret_cast<uint32_t*>(smem + SM_BLO + byt + 16);
            }
            // 3 sweeps of 16 independent mmas
#pragma unroll
            for (int mt = 0; mt < 2; mt++)
#pragma unroll
                for (int nt = 0; nt < 8; nt++)
                    mma16816(acc[mt][nt], ahi[mt], bhi[nt]);
#pragma unroll
            for (int mt = 0; mt < 2; mt++)
#pragma unroll
                for (int nt = 0; nt < 8; nt++)
                    mma16816(acc[mt][nt], alo[mt], bhi[nt]);
#pragma unroll
            for (int mt = 0; mt < 2; mt++)
#pragma unroll
                for (int nt = 0; nt < 8; nt++)
                    mma16816(acc[mt][nt], ahi[mt], blo[nt]);
        }
        __syncthreads();
    }

    // ---- epilogue: + bias, row L2 norm, store ----
    const float* bsm = reinterpret_cast<const float*>(smem + SM_BIAS);
    float ssq[2][2] = {{0.f, 0.f}, {0.f, 0.f}};
#pragma unroll
    for (int mt = 0; mt < 2; mt++)
#pragma unroll
        for (int nt = 0; nt < 8; nt++) {
            int col = wn * 64 + nt * 8 + 2 * c4;
            float b0 = bsm[col], b1 = bsm[col + 1];
            float* d = acc[mt][nt];
            d[0] += b0; d[1] += b1; d[2] += b0; d[3] += b1;
            ssq[mt][0] += d[0] * d[0] + d[1] * d[1];
            ssq[mt][1] += d[2] * d[2] + d[3] * d[3];
        }
    // reduce across the 4 lanes (c4) sharing each row
#pragma unroll
    for (int off = 1; off <= 2; off <<= 1) {
        ssq[0][0] += __shfl_xor_sync(0xFFFFFFFFu, ssq[0][0], off);
        ssq[0][1] += __shfl_xor_sync(0xFFFFFFFFu, ssq[0][1], off);
        ssq[1][0] += __shfl_xor_sync(0xFFFFFFFFu, ssq[1][0], off);
        ssq[1][1] += __shfl_xor_sync(0xFFFFFFFFu, ssq[1][1], off);
    }
    float* rp = reinterpret_cast<float*>(smem + SM_RED);   // [4 warps_n][64 rows]
    if (c4 == 0) {
#pragma unroll
        for (int mt = 0; mt < 2; mt++)
#pragma unroll
            for (int h = 0; h < 2; h++)
                rp[wn * 64 + wm * 32 + mt * 16 + r4 + 8 * h] = ssq[mt][h];
    }
    __syncthreads();

#pragma unroll
    for (int mt = 0; mt < 2; mt++)
#pragma unroll
        for (int h = 0; h < 2; h++) {
            int rr = wm * 32 + mt * 16 + r4 + 8 * h;
            float s = rp[rr] + rp[64 + rr] + rp[128 + rr] + rp[192 + rr];
            float invn = 1.0f / fmaxf(sqrtf(s), 1e-12f);
            int row = node0 + rr;
            if (row < N_NODES) {
#pragma unroll
                for (int nt = 0; nt < 8; nt++) {
                    float* d = acc[mt][nt];
                    float2 o;
                    o.x = d[2 * h]     * invn;
                    o.y = d[2 * h + 1] * invn;
                    *reinterpret_cast<float2*>(out + (size_t)row * C_OUT + wn * 64 + nt * 8 + 2 * c4) = o;
                }
            }
        }
}

// ---------------- launch ------------------------------------------------------
extern "C" void kernel_launch(void* const* d_in, const int* in_sizes, int n_in,
                              void* d_out, int out_size) {
    const float*     x    = (const float*)d_in[0];      // [100000,128]
    const long long* ei   = (const long long*)d_in[1];  // [2,600000]
    const float*     W    = (const float*)d_in[2];      // [256,256]
    const float*     bias = (const float*)d_in[3];      // [1,256]
    float*           out  = (float*)d_out;              // [100000,256]

    detect_kernel<<<1, 1>>>(ei);

    {
        int tot = N_NODES * D_FEAT / 4;
        zero_kernel<<<(tot + 255) / 256, 256>>>();
    }

    prep_w_kernel<<<256, 256>>>(W);

    {
        long long threads = (long long)E_EDGES * 32;
        scatter_kernel<<<(int)((threads + 255) / 256), 256>>>(x, ei);
    }

    {
        cudaFuncSetAttribute(gemm_hmma_kernel, cudaFuncAttributeMaxDynamicSharedMemorySize, SM_TOT);
        int grid = (N_NODES + 63) / 64;                 // 1563
        gemm_hmma_kernel<<<grid, 256, SM_TOT>>>(x, bias, out);
    }
}

// round 8
// speedup vs baseline: 2.3103x; 1.0820x over previous
#include <cuda_runtime.h>
#include <cuda_bf16.h>
#include <math.h>
#include <stdint.h>

#define N_NODES 100000
#define D_FEAT  128
#define E_EDGES 600000
#define C_OUT   256

// ---------------- scratch (no allocs allowed; __device__ globals) -------------
__device__ __align__(16) float g_sums[(size_t)N_NODES * D_FEAT];   // 51.2 MB
__device__ float g_cnt[N_NODES];
__device__ int   g_idx64;
// W pre-transposed + bf16 hi/lo split: [n][k] rows of 256 bf16 (512B)
__device__ __align__(16) unsigned char g_Bhi_t[256 * 512];
__device__ __align__(16) unsigned char g_Blo_t[256 * 512];

// ---------------- index-width detection --------------------------------------
__global__ void detect_kernel(const long long* __restrict__ ei) {
    int ok = 1;
#pragma unroll
    for (int i = 0; i < 8; i++) {
        long long v = ei[i];
        if (v < 0 || v >= (long long)N_NODES) ok = 0;
    }
    g_idx64 = ok;
}

// ---------------- zero scratch ------------------------------------------------
__global__ void zero_kernel() {
    int i = blockIdx.x * blockDim.x + threadIdx.x;
    const int TOT4 = N_NODES * D_FEAT / 4;
    if (i < TOT4) reinterpret_cast<float4*>(g_sums)[i] = make_float4(0.f, 0.f, 0.f, 0.f);
    if (i < N_NODES) g_cnt[i] = 0.f;
}

// ---------------- W prep: transpose + bf16 hi/lo split ------------------------
__global__ void prep_w_kernel(const float* __restrict__ W) {
    int n = blockIdx.x;        // 0..255
    int k = threadIdx.x;       // 0..255
    float w = W[k * C_OUT + n];
    __nv_bfloat16 hi = __float2bfloat16(w);
    __nv_bfloat16 lo = __float2bfloat16(w - __bfloat162float(hi));
    reinterpret_cast<__nv_bfloat16*>(g_Bhi_t)[n * 256 + k] = hi;
    reinterpret_cast<__nv_bfloat16*>(g_Blo_t)[n * 256 + k] = lo;
}

// ---------------- vector reduction helper ------------------------------------
__device__ __forceinline__ void red_add_v4(float* p, float4 v) {
    asm volatile("red.global.add.v4.f32 [%0], {%1, %2, %3, %4};"
                 :: "l"(p), "f"(v.x), "f"(v.y), "f"(v.z), "f"(v.w) : "memory");
}

// ---------------- edge scatter: 4 edges per warp (MLP=4 on gathers) ----------
#define EPW 4
__global__ void scatter_kernel(const float* __restrict__ x,
                               const long long* __restrict__ ei) {
    const int warp = (blockIdx.x * blockDim.x + threadIdx.x) >> 5;
    const int lane = threadIdx.x & 31;
    const int e0 = warp * EPW;
    if (e0 >= E_EDGES) return;

    const int use64 = g_idx64;
    int r[EPW], c[EPW];
#pragma unroll
    for (int i = 0; i < EPW; i++) {
        int e = e0 + i;                      // E_EDGES % EPW == 0: always valid
        if (use64) {
            r[i] = (int)ei[e];
            c[i] = (int)ei[E_EDGES + e];
        } else {
            const int* p = (const int*)ei;
            r[i] = p[e];
            c[i] = p[E_EDGES + e];
        }
    }

    // issue all gathers first (independent -> MLP=EPW)
    float4 v[EPW];
#pragma unroll
    for (int i = 0; i < EPW; i++)
        if (r[i] != c[i])
            v[i] = *reinterpret_cast<const float4*>(x + (size_t)c[i] * D_FEAT + lane * 4);

#pragma unroll
    for (int i = 0; i < EPW; i++) {
        if (r[i] != c[i]) {
            red_add_v4(g_sums + (size_t)r[i] * D_FEAT + lane * 4, v[i]);
            if (lane == 0) atomicAdd(&g_cnt[r[i]], 1.0f);
        }
    }
}

// ---------------- HMMA GEMM: (mean||x) @ W + bias + row-L2-normalize ---------
// BM=64, BN=256, 256 threads = 8 warps as 2(M)x4(N); warp tile 32x64.
// mma.sync m16n8k16 bf16->f32, 3-pass hi/lo split. K chunked 128 x 2.
// smem rows padded to 272B (136 bf16): frag LDS bank = (4r+c)%32, conflict-free.
#define ROWB 272
#define ROWH 136
#define SM_BIAS 0
#define SM_RED  1024
#define SM_AHI  2048
#define SM_ALO  (SM_AHI + 64 * ROWB)      // 19456
#define SM_BHI  (SM_ALO + 64 * ROWB)      // 36864
#define SM_BLO  (SM_BHI + 256 * ROWB)     // 106496
#define SM_TOT  (SM_BLO + 256 * ROWB)     // 176128

__device__ __forceinline__ void mma16816(float d[4], const uint32_t a[4], const uint32_t b[2]) {
    asm volatile("mma.sync.aligned.m16n8k16.row.col.f32.bf16.bf16.f32 "
                 "{%0,%1,%2,%3}, {%4,%5,%6,%7}, {%8,%9}, {%0,%1,%2,%3};"
                 : "+f"(d[0]), "+f"(d[1]), "+f"(d[2]), "+f"(d[3])
                 : "r"(a[0]), "r"(a[1]), "r"(a[2]), "r"(a[3]), "r"(b[0]), "r"(b[1]));
}

__global__ void __launch_bounds__(256) gemm_hmma_kernel(const float* __restrict__ x,
                                                        const float* __restrict__ bias,
                                                        float* __restrict__ out) {
    extern __shared__ __align__(16) unsigned char smem[];
    const int tid = threadIdx.x;
    const int wid = tid >> 5;
    const int lid = tid & 31;
    const int wm  = wid >> 2;            // 0..1 : rows wm*32..+31
    const int wn  = wid & 3;             // 0..3 : cols wn*64..+63
    const int r4  = lid >> 2;            // 0..7
    const int c4  = lid & 3;             // 0..3
    const int node0 = blockIdx.x * 64;

    // stage bias
    reinterpret_cast<float*>(smem + SM_BIAS)[tid] = bias[tid];

    // A staging role: row = tid>>2 (0..63), k-base = (tid&3)*32 within 128-chunk
    const int arow = tid >> 2;
    const int akb  = (tid & 3) * 32;
    const int amg  = node0 + arow;
    const bool a_ok = (amg < N_NODES);
    const float inv_cnt = a_ok ? (1.0f / fmaxf(g_cnt[amg], 1.0f)) : 0.f;

    float acc[2][8][4];
#pragma unroll
    for (int mt = 0; mt < 2; mt++)
#pragma unroll
        for (int nt = 0; nt < 8; nt++)
#pragma unroll
            for (int q = 0; q < 4; q++) acc[mt][nt][q] = 0.f;

    const uint4* gbh = reinterpret_cast<const uint4*>(g_Bhi_t);
    const uint4* gbl = reinterpret_cast<const uint4*>(g_Blo_t);

#pragma unroll 1
    for (int c = 0; c < 2; c++) {
        // ---- stage A (hi/lo split) ----
        {
            const float* asrc = (c == 0) ? (g_sums + (size_t)amg * D_FEAT + akb)
                                         : (x      + (size_t)amg * D_FEAT + akb);
            const float scale = (c == 0) ? inv_cnt : 1.0f;
#pragma unroll
            for (int q = 0; q < 8; q++) {
                float4 v = make_float4(0.f, 0.f, 0.f, 0.f);
                if (a_ok) {
                    v = *reinterpret_cast<const float4*>(asrc + q * 4);
                    v.x *= scale; v.y *= scale; v.z *= scale; v.w *= scale;
                }
                __nv_bfloat16 hx = __float2bfloat16(v.x), hy = __float2bfloat16(v.y);
                __nv_bfloat16 hz = __float2bfloat16(v.z), hw = __float2bfloat16(v.w);
                __nv_bfloat16 lx = __float2bfloat16(v.x - __bfloat162float(hx));
                __nv_bfloat16 ly = __float2bfloat16(v.y - __bfloat162float(hy));
                __nv_bfloat16 lz = __float2bfloat16(v.z - __bfloat162float(hz));
                __nv_bfloat16 lw = __float2bfloat16(v.w - __bfloat162float(hw));
                uint32_t hi0 = (uint32_t)__bfloat16_as_ushort(hx) | ((uint32_t)__bfloat16_as_ushort(hy) << 16);
                uint32_t hi1 = (uint32_t)__bfloat16_as_ushort(hz) | ((uint32_t)__bfloat16_as_ushort(hw) << 16);
                uint32_t lo0 = (uint32_t)__bfloat16_as_ushort(lx) | ((uint32_t)__bfloat16_as_ushort(ly) << 16);
                uint32_t lo1 = (uint32_t)__bfloat16_as_ushort(lz) | ((uint32_t)__bfloat16_as_ushort(lw) << 16);
                uint32_t byt = (uint32_t)(arow * ROWH + akb + q * 4) * 2;
                *reinterpret_cast<uint32_t*>(smem + SM_AHI + byt)     = hi0;
                *reinterpret_cast<uint32_t*>(smem + SM_AHI + byt + 4) = hi1;
                *reinterpret_cast<uint32_t*>(smem + SM_ALO + byt)     = lo0;
                *reinterpret_cast<uint32_t*>(smem + SM_ALO + byt + 4) = lo1;
            }
        }
        // ---- stage B (coalesced copy of 128-bf16 slices) ----
#pragma unroll
        for (int i = 0; i < 16; i++) {
            int f = i * 256 + tid;           // 0..4095
            int n = f >> 4;
            int j = f & 15;
            *reinterpret_cast<uint4*>(smem + SM_BHI + n * ROWB + j * 16) = gbh[n * 32 + c * 16 + j];
            *reinterpret_cast<uint4*>(smem + SM_BLO + n * ROWB + j * 16) = gbl[n * 32 + c * 16 + j];
        }
        __syncthreads();

        // ---- compute: 8 k-steps of 16 ----
#pragma unroll
        for (int ks = 0; ks < 8; ks++) {
            const int kb = ks * 16;
            uint32_t ahi[2][4], alo[2][4];
#pragma unroll
            for (int mt = 0; mt < 2; mt++) {
                int row0 = wm * 32 + mt * 16 + r4;
                uint32_t byt = (uint32_t)(row0 * ROWH + kb + 2 * c4) * 2;
                ahi[mt][0] = *reinterpret_cast<uint32_t*>(smem + SM_AHI + byt);
                ahi[mt][1] = *reinterpret_cast<uint32_t*>(smem + SM_AHI + byt + 8 * ROWB);
                ahi[mt][2] = *reinterpret_cast<uint32_t*>(smem + SM_AHI + byt + 16);
                ahi[mt][3] = *reinterpret_cast<uint32_t*>(smem + SM_AHI + byt + 8 * ROWB + 16);
                alo[mt][0] = *reinterpret_cast<uint32_t*>(smem + SM_ALO + byt);
                alo[mt][1] = *reinterpret_cast<uint32_t*>(smem + SM_ALO + byt + 8 * ROWB);
                alo[mt][2] = *reinterpret_cast<uint32_t*>(smem + SM_ALO + byt + 16);
                alo[mt][3] = *reinterpret_cast<uint32_t*>(smem + SM_ALO + byt + 8 * ROWB + 16);
            }
            uint32_t bhi[8][2], blo[8][2];
#pragma unroll
            for (int nt = 0; nt < 8; nt++) {
                int n = wn * 64 + nt * 8 + r4;
                uint32_t byt = (uint32_t)(n * ROWH + kb + 2 * c4) * 2;
                bhi[nt][0] = *reinterpret_cast<uint32_t*>(smem + SM_BHI + byt);
                bhi[nt][1] = *reinterpret_cast<uint32_t*>(smem + SM_BHI + byt + 16);
                blo[nt][0] = *reinterpret_cast<uint32_t*>(smem + SM_BLO + byt);
                blo[nt][1] = *reinterpret_cast<uint32_t*>(smem + SM_BLO + byt + 16);
            }
            // 3 sweeps of 16 independent mmas
#pragma unroll
            for (int mt = 0; mt < 2; mt++)
#pragma unroll
                for (int nt = 0; nt < 8; nt++)
                    mma16816(acc[mt][nt], ahi[mt], bhi[nt]);
#pragma unroll
            for (int mt = 0; mt < 2; mt++)
#pragma unroll
                for (int nt = 0; nt < 8; nt++)
                    mma16816(acc[mt][nt], alo[mt], bhi[nt]);
#pragma unroll
            for (int mt = 0; mt < 2; mt++)
#pragma unroll
                for (int nt = 0; nt < 8; nt++)
                    mma16816(acc[mt][nt], ahi[mt], blo[nt]);
        }
        __syncthreads();
    }

    // ---- epilogue: + bias, row L2 norm, store ----
    const float* bsm = reinterpret_cast<const float*>(smem + SM_BIAS);
    float ssq[2][2] = {{0.f, 0.f}, {0.f, 0.f}};
#pragma unroll
    for (int mt = 0; mt < 2; mt++)
#pragma unroll
        for (int nt = 0; nt < 8; nt++) {
            int col = wn * 64 + nt * 8 + 2 * c4;
            float b0 = bsm[col], b1 = bsm[col + 1];
            float* d = acc[mt][nt];
            d[0] += b0; d[1] += b1; d[2] += b0; d[3] += b1;
            ssq[mt][0] += d[0] * d[0] + d[1] * d[1];
            ssq[mt][1] += d[2] * d[2] + d[3] * d[3];
        }
    // reduce across the 4 lanes (c4) sharing each row
#pragma unroll
    for (int off = 1; off <= 2; off <<= 1) {
        ssq[0][0] += __shfl_xor_sync(0xFFFFFFFFu, ssq[0][0], off);
        ssq[0][1] += __shfl_xor_sync(0xFFFFFFFFu, ssq[0][1], off);
        ssq[1][0] += __shfl_xor_sync(0xFFFFFFFFu, ssq[1][0], off);
        ssq[1][1] += __shfl_xor_sync(0xFFFFFFFFu, ssq[1][1], off);
    }
    float* rp = reinterpret_cast<float*>(smem + SM_RED);   // [4 warps_n][64 rows]
    if (c4 == 0) {
#pragma unroll
        for (int mt = 0; mt < 2; mt++)
#pragma unroll
            for (int h = 0; h < 2; h++)
                rp[wn * 64 + wm * 32 + mt * 16 + r4 + 8 * h] = ssq[mt][h];
    }
    __syncthreads();

#pragma unroll
    for (int mt = 0; mt < 2; mt++)
#pragma unroll
        for (int h = 0; h < 2; h++) {
            int rr = wm * 32 + mt * 16 + r4 + 8 * h;
            float s = rp[rr] + rp[64 + rr] + rp[128 + rr] + rp[192 + rr];
            float invn = 1.0f / fmaxf(sqrtf(s), 1e-12f);
            int row = node0 + rr;
            if (row < N_NODES) {
#pragma unroll
                for (int nt = 0; nt < 8; nt++) {
                    float* d = acc[mt][nt];
                    float2 o;
                    o.x = d[2 * h]     * invn;
                    o.y = d[2 * h + 1] * invn;
                    *reinterpret_cast<float2*>(out + (size_t)row * C_OUT + wn * 64 + nt * 8 + 2 * c4) = o;
                }
            }
        }
}

// ---------------- launch ------------------------------------------------------
extern "C" void kernel_launch(void* const* d_in, const int* in_sizes, int n_in,
                              void* d_out, int out_size) {
    const float*     x    = (const float*)d_in[0];      // [100000,128]
    const long long* ei   = (const long long*)d_in[1];  // [2,600000]
    const float*     W    = (const float*)d_in[2];      // [256,256]
    const float*     bias = (const float*)d_in[3];      // [1,256]
    float*           out  = (float*)d_out;              // [100000,256]

    detect_kernel<<<1, 1>>>(ei);

    {
        int tot = N_NODES * D_FEAT / 4;
        zero_kernel<<<(tot + 255) / 256, 256>>>();
    }

    prep_w_kernel<<<256, 256>>>(W);

    {
        // EPW edges per warp: warps = E/EPW = 150000, threads = 4.8M
        long long threads = (long long)(E_EDGES / EPW) * 32;
        scatter_kernel<<<(int)((threads + 255) / 256), 256>>>(x, ei);
    }

    {
        cudaFuncSetAttribute(gemm_hmma_kernel, cudaFuncAttributeMaxDynamicSharedMemorySize, SM_TOT);
        int grid = (N_NODES + 63) / 64;                 // 1563
        gemm_hmma_kernel<<<grid, 256, SM_TOT>>>(x, bias, out);
    }
}